// round 5
// baseline (speedup 1.0000x reference)
#include <cuda_runtime.h>
#include <cuda_fp16.h>
#include <cuda_bf16.h>
#include <cstdint>

// MeanAggregator: out[i,:] = mean_{e<EPN} features[edge_dst[i*EPN+e], :], D=128.
// R5 (= R4 resubmit; R4 hit an infra container failure): the kernel is
// byte-bound through L2/L1tex (three scheduling variants -> identical 28.8us,
// L2=62%). Halve the gathered bytes: convert the 100000x128 fp32 table to fp16
// in __device__ scratch (25.6 MB) each launch, then gather 256B/row.
// Accumulation stays fp32. Expected rel_err ~2e-4 (< 1e-3 gate).

#define D_DIM 128
#define N_CAP 100000          // capacity of the fp16 scratch table (rows)

// fp16 feature cache: N_CAP * 128 halves = 25.6 MB, stored as uint2 (8B = 4 halves).
// Element i of g_feat16 holds halves [4i, 4i+4) of the flattened table.
__device__ uint2 g_feat16[(size_t)N_CAP * (D_DIM / 4)];

// ---------------- conversion: fp32 table -> fp16 scratch (grid-stride) -------
__global__ __launch_bounds__(256) void convert_f32_to_f16(
    const float* __restrict__ feat, int n4)   // n4 = total floats / 4
{
    const int stride = gridDim.x * blockDim.x;
    for (int i = blockIdx.x * blockDim.x + threadIdx.x; i < n4; i += stride) {
        const float4 f = __ldg(reinterpret_cast<const float4*>(feat) + i);
        const __half2 h0 = __floats2half2_rn(f.x, f.y);
        const __half2 h1 = __floats2half2_rn(f.z, f.w);
        uint2 u;
        u.x = *reinterpret_cast<const uint32_t*>(&h0);
        u.y = *reinterpret_cast<const uint32_t*>(&h1);
        g_feat16[i] = u;
    }
}

// ---------------- gather from fp16 cache ----------------
// One warp per node; lane l owns columns [4l, 4l+4) -> one uint2 (4 halves) per row.
template <int EPN>
__global__ __launch_bounds__(256) void mean_agg_f16(
    const int* __restrict__ edge_dst,
    float*     __restrict__ out,
    int B)
{
    const int warp = (blockIdx.x * blockDim.x + threadIdx.x) >> 5;
    const int lane = threadIdx.x & 31;
    if (warp >= B) return;

    static_assert(EPN <= 32, "index-shuffle needs EPN <= 32");
    const int* __restrict__ idx = edge_dst + (size_t)warp * EPN;
    int myidx = 0;
    if (lane < EPN) myidx = __ldg(idx + lane);

    float4 acc = make_float4(0.f, 0.f, 0.f, 0.f);

#pragma unroll
    for (int e = 0; e < EPN; ++e) {
        const int nb = __shfl_sync(0xFFFFFFFFu, myidx, e);
        const uint2 u = __ldg(g_feat16 + (size_t)nb * (D_DIM / 4) + lane);
        const __half2 h0 = *reinterpret_cast<const __half2*>(&u.x);
        const __half2 h1 = *reinterpret_cast<const __half2*>(&u.y);
        const float2 a = __half22float2(h0);
        const float2 b = __half22float2(h1);
        acc.x += a.x; acc.y += a.y; acc.z += b.x; acc.w += b.y;
    }

    const float inv = 1.0f / (float)EPN;
    acc.x *= inv; acc.y *= inv; acc.z *= inv; acc.w *= inv;
    reinterpret_cast<float4*>(out + (size_t)warp * D_DIM)[lane] = acc;
}

// ---------------- fp32 fallback (proven R1 path) ----------------
__global__ __launch_bounds__(256) void mean_agg_f32_dyn(
    const float* __restrict__ feat,
    const int*   __restrict__ edge_dst,
    float*       __restrict__ out,
    int B, int epn)
{
    const int warp = (blockIdx.x * blockDim.x + threadIdx.x) >> 5;
    const int lane = threadIdx.x & 31;
    if (warp >= B) return;

    const int* __restrict__ idx = edge_dst + (size_t)warp * epn;
    float4 acc = make_float4(0.f, 0.f, 0.f, 0.f);
#pragma unroll 4
    for (int e = 0; e < epn; ++e) {
        const int nb = __ldg(idx + e);
        const float4 v = __ldg(reinterpret_cast<const float4*>(
                                   feat + (size_t)nb * D_DIM) + lane);
        acc.x += v.x; acc.y += v.y; acc.z += v.z; acc.w += v.w;
    }
    const float inv = 1.0f / (float)epn;
    acc.x *= inv; acc.y *= inv; acc.z *= inv; acc.w *= inv;
    reinterpret_cast<float4*>(out + (size_t)warp * D_DIM)[lane] = acc;
}

extern "C" void kernel_launch(void* const* d_in, const int* in_sizes, int n_in,
                              void* d_out, int out_size)
{
    const float* feat     = (const float*)d_in[0];
    const int*   edge_dst = (const int*)d_in[2];
    float*       out      = (float*)d_out;

    const int B       = out_size / D_DIM;      // 50000
    const int E       = in_sizes[2];           // 850000
    const int epn     = E / B;                 // 17
    const int n_feat  = in_sizes[0];           // N_TOTAL * D
    const int n_rows  = n_feat / D_DIM;        // 100000

    const int threads = 256;
    const int blocks  = (B * 32 + threads - 1) / threads;

    if (epn == 17 && n_rows <= N_CAP && n_feat % 4 == 0) {
        const int n4 = n_feat / 4;             // 3.2M float4s
        convert_f32_to_f16<<<2048, threads>>>(feat, n4);
        mean_agg_f16<17><<<blocks, threads>>>(edge_dst, out, B);
    } else {
        mean_agg_f32_dyn<<<blocks, threads>>>(feat, edge_dst, out, B, epn);
    }
}

// round 6
// speedup vs baseline: 1.2056x; 1.2056x over previous
#include <cuda_runtime.h>
#include <cuda_bf16.h>
#include <cstdint>

// MeanAggregator: out[i,:] = mean_{e<EPN} features[edge_dst[i*EPN+e], :], D=128 f32.
// R6: R1-R3 sat exactly on the L1tex within-LDG wavefront-replay floor:
// LDG.128 = 4 wavefronts at 2.07 cyc each (~29us retrodicted vs 28.7 measured).
// Different LDGs pipeline at 1.0 cyc/wf, so split each row gather into two
// LDG.64 (float2) loads: 2 x (1 + 2.07) = 6.1 wf-cyc/row vs 7.2+ for LDG.128,
// and more importantly the 4-wf replay burst is broken up. LSU floor stays
// clear (~12us); full LDG.32 split rejected (LSU floor ~24us).
// Single kernel, pure fp32 -> rel_err back to ~1e-7.

#define D_DIM 128

template <int EPN>
__global__ __launch_bounds__(256) void mean_agg_kernel_fixed(
    const float* __restrict__ feat,
    const int*   __restrict__ edge_dst,
    float*       __restrict__ out,
    int B)
{
    const int warp = (blockIdx.x * blockDim.x + threadIdx.x) >> 5;
    const int lane = threadIdx.x & 31;
    if (warp >= B) return;

    static_assert(EPN <= 32, "index-shuffle needs EPN <= 32");

    // One coalesced index load per warp; broadcast via shuffle.
    const int* __restrict__ idx = edge_dst + (size_t)warp * EPN;
    int myidx = 0;
    if (lane < EPN) myidx = __ldg(idx + lane);

    // Lane l owns float2 slots l (bytes [8l,8l+8)) and l+32 (bytes 256+...).
    float2 acc0 = make_float2(0.f, 0.f);
    float2 acc1 = make_float2(0.f, 0.f);

#pragma unroll
    for (int e = 0; e < EPN; ++e) {
        const int nb = __shfl_sync(0xFFFFFFFFu, myidx, e);
        const float2* __restrict__ row =
            reinterpret_cast<const float2*>(feat + (size_t)nb * D_DIM);
        const float2 v0 = __ldg(row + lane);        // first 256B of row
        const float2 v1 = __ldg(row + 32 + lane);   // second 256B of row
        acc0.x += v0.x; acc0.y += v0.y;
        acc1.x += v1.x; acc1.y += v1.y;
    }

    const float inv = 1.0f / (float)EPN;
    acc0.x *= inv; acc0.y *= inv;
    acc1.x *= inv; acc1.y *= inv;

    float2* __restrict__ orow =
        reinterpret_cast<float2*>(out + (size_t)warp * D_DIM);
    orow[lane]      = acc0;
    orow[32 + lane] = acc1;
}

// General fallback: runtime EPN, same float2 split.
__global__ __launch_bounds__(256) void mean_agg_kernel_dyn(
    const float* __restrict__ feat,
    const int*   __restrict__ edge_dst,
    float*       __restrict__ out,
    int B, int epn)
{
    const int warp = (blockIdx.x * blockDim.x + threadIdx.x) >> 5;
    const int lane = threadIdx.x & 31;
    if (warp >= B) return;

    const int* __restrict__ idx = edge_dst + (size_t)warp * epn;

    float2 acc0 = make_float2(0.f, 0.f);
    float2 acc1 = make_float2(0.f, 0.f);

#pragma unroll 4
    for (int e = 0; e < epn; ++e) {
        const int nb = __ldg(idx + e);
        const float2* __restrict__ row =
            reinterpret_cast<const float2*>(feat + (size_t)nb * D_DIM);
        const float2 v0 = __ldg(row + lane);
        const float2 v1 = __ldg(row + 32 + lane);
        acc0.x += v0.x; acc0.y += v0.y;
        acc1.x += v1.x; acc1.y += v1.y;
    }

    const float inv = 1.0f / (float)epn;
    acc0.x *= inv; acc0.y *= inv;
    acc1.x *= inv; acc1.y *= inv;

    float2* __restrict__ orow =
        reinterpret_cast<float2*>(out + (size_t)warp * D_DIM);
    orow[lane]      = acc0;
    orow[32 + lane] = acc1;
}

extern "C" void kernel_launch(void* const* d_in, const int* in_sizes, int n_in,
                              void* d_out, int out_size)
{
    const float* feat     = (const float*)d_in[0];
    const int*   edge_dst = (const int*)d_in[2];
    float*       out      = (float*)d_out;

    const int B   = out_size / D_DIM;   // 50000
    const int E   = in_sizes[2];        // 850000
    const int epn = E / B;              // 17

    const int threads = 256;            // 8 warps/block
    const int blocks  = (B * 32 + threads - 1) / threads;

    if (epn == 17) {
        mean_agg_kernel_fixed<17><<<blocks, threads>>>(feat, edge_dst, out, B);
    } else {
        mean_agg_kernel_dyn<<<blocks, threads>>>(feat, edge_dst, out, B, epn);
    }
}